// round 1
// baseline (speedup 1.0000x reference)
#include <cuda_runtime.h>
#include <math.h>

#define NU 100000
#define NI 50000
#define NT 10000
#define NNODES 160000
#define NE 800000
#define DD 64

// ---------------- device scratch (no allocations allowed) ----------------
__device__ float g_embsA[NNODES * DD];
__device__ float g_embsB[NNODES * DD];
__device__ float g_offA[NNODES * DD];
__device__ float g_offB[NNODES * DD];
__device__ float g_Hn[NNODES * DD];

__device__ int g_deg[NNODES];
__device__ int g_scan[NNODES];
__device__ int g_csr_off[NNODES + 1];
__device__ int g_pos[NNODES];
__device__ int g_csr_tail[NE];
__device__ int g_bsums[256];

// ---------------- CSR build ----------------
__global__ void zero_deg_kernel() {
    int i = blockIdx.x * blockDim.x + threadIdx.x;
    if (i < NNODES) g_deg[i] = 0;
}

__global__ void hist_kernel(const int* __restrict__ head) {
    int e = blockIdx.x * blockDim.x + threadIdx.x;
    if (e < NE) atomicAdd(&g_deg[head[e]], 1);
}

#define SCAN_B 1024
__global__ void scan_block_kernel() {
    __shared__ int sh[SCAN_B];
    int g = blockIdx.x * SCAN_B + threadIdx.x;
    int v = (g < NNODES) ? g_deg[g] : 0;
    sh[threadIdx.x] = v;
    __syncthreads();
    for (int of = 1; of < SCAN_B; of <<= 1) {
        int t = (threadIdx.x >= of) ? sh[threadIdx.x - of] : 0;
        __syncthreads();
        sh[threadIdx.x] += t;
        __syncthreads();
    }
    if (g < NNODES) g_scan[g] = sh[threadIdx.x];
    if (threadIdx.x == SCAN_B - 1) g_bsums[blockIdx.x] = sh[threadIdx.x];
}

__global__ void scan_sums_kernel(int nb) {
    if (threadIdx.x == 0 && blockIdx.x == 0) {
        int acc = 0;
        for (int i = 0; i < nb; i++) { int v = g_bsums[i]; g_bsums[i] = acc; acc += v; }
        g_csr_off[0] = 0;
    }
}

__global__ void scan_add_kernel() {
    int g = blockIdx.x * SCAN_B + threadIdx.x;
    if (g < NNODES) g_csr_off[g + 1] = g_scan[g] + g_bsums[blockIdx.x];
}

__global__ void pos_init_kernel() {
    int i = blockIdx.x * blockDim.x + threadIdx.x;
    if (i < NNODES) g_pos[i] = g_csr_off[i];
}

__global__ void scatter_kernel(const int* __restrict__ head, const int* __restrict__ tail) {
    int e = blockIdx.x * blockDim.x + threadIdx.x;
    if (e < NE) {
        int h = head[e];
        int p = atomicAdd(&g_pos[h], 1);
        g_csr_tail[p] = tail[e];
    }
}

// ---------------- init: concat embeddings + relu(concat offsets) ----------------
__global__ void init_kernel(const float4* __restrict__ ue, const float4* __restrict__ uo,
                            const float4* __restrict__ ie, const float4* __restrict__ io,
                            const float4* __restrict__ te, const float4* __restrict__ to) {
    int idx = blockIdx.x * blockDim.x + threadIdx.x;  // over NNODES*16 float4s
    if (idx >= NNODES * 16) return;
    float4 e, o;
    if (idx < NU * 16) { e = ue[idx]; o = uo[idx]; }
    else if (idx < (NU + NI) * 16) { e = ie[idx - NU * 16]; o = io[idx - NU * 16]; }
    else { e = te[idx - (NU + NI) * 16]; o = to[idx - (NU + NI) * 16]; }
    o.x = fmaxf(o.x, 0.f); o.y = fmaxf(o.y, 0.f);
    o.z = fmaxf(o.z, 0.f); o.w = fmaxf(o.w, 0.f);
    ((float4*)g_embsA)[idx] = e;
    ((float4*)g_offA)[idx]  = o;
}

// ---------------- fused 2-stage MLP (per-node): Hn = relu(X@W1^T+b1)@W2^T+b2 ----------------
// 64 rows x 64 cols per block, 256 threads, 4x4 register tile per thread.
// W kept transposed in shared with an xor-swizzle so the k-loop does one conflict-free
// LDS.128 for 4 W values, while X/h reads are warp broadcasts.
__device__ __forceinline__ int wswz(int k, int j) {
    return k * 64 + ((((j >> 2) ^ (k & 15)) << 2) | (j & 3));
}

__global__ __launch_bounds__(256) void mlp_kernel(int src,
                                                  const float* __restrict__ W1,
                                                  const float* __restrict__ b1,
                                                  const float* __restrict__ W2,
                                                  const float* __restrict__ b2) {
    __shared__ float Ws[64 * 64];
    __shared__ float Xs[64 * 64];
    __shared__ float bs[64];

    const float* __restrict__ X = src ? g_embsB : g_embsA;
    float* __restrict__ Y = g_Hn;

    int tid = threadIdx.x;
    int row0 = blockIdx.x * 64;

    // Ws := W1 transposed+swizzled (coalesced global reads)
    for (int i = tid; i < 4096; i += 256) {
        int j = i >> 6, k = i & 63;          // read W1[j][k] coalesced over k
        Ws[wswz(k, j)] = W1[i];
    }
    if (tid < 64) bs[tid] = b1[tid];
    {
        const float4* Xg = (const float4*)(X + (size_t)row0 * 64);
        float4* Xs4 = (float4*)Xs;
        for (int i = tid; i < 1024; i += 256) Xs4[i] = Xg[i];
    }
    __syncthreads();

    int tx = tid & 15, ty = tid >> 4;
    int j0 = tx * 4, r0 = ty * 4;
    float acc[4][4];

#pragma unroll
    for (int i = 0; i < 4; i++)
#pragma unroll
        for (int j = 0; j < 4; j++) acc[i][j] = bs[j0 + j];

#pragma unroll 8
    for (int k = 0; k < 64; k++) {
        float4 w = *(const float4*)&Ws[k * 64 + ((tx ^ (k & 15)) << 2)];
        float x0 = Xs[(r0 + 0) * 64 + k];
        float x1 = Xs[(r0 + 1) * 64 + k];
        float x2 = Xs[(r0 + 2) * 64 + k];
        float x3 = Xs[(r0 + 3) * 64 + k];
        acc[0][0] += x0 * w.x; acc[0][1] += x0 * w.y; acc[0][2] += x0 * w.z; acc[0][3] += x0 * w.w;
        acc[1][0] += x1 * w.x; acc[1][1] += x1 * w.y; acc[1][2] += x1 * w.z; acc[1][3] += x1 * w.w;
        acc[2][0] += x2 * w.x; acc[2][1] += x2 * w.y; acc[2][2] += x2 * w.z; acc[2][3] += x2 * w.w;
        acc[3][0] += x3 * w.x; acc[3][1] += x3 * w.y; acc[3][2] += x3 * w.z; acc[3][3] += x3 * w.w;
    }
    __syncthreads();

    // h (relu) -> Xs; reload Ws with W2 transposed
#pragma unroll
    for (int i = 0; i < 4; i++) {
        float4 h = make_float4(fmaxf(acc[i][0], 0.f), fmaxf(acc[i][1], 0.f),
                               fmaxf(acc[i][2], 0.f), fmaxf(acc[i][3], 0.f));
        *(float4*)&Xs[(r0 + i) * 64 + j0] = h;
    }
    for (int i = tid; i < 4096; i += 256) {
        int j = i >> 6, k = i & 63;
        Ws[wswz(k, j)] = W2[i];
    }
    if (tid < 64) bs[tid] = b2[tid];
    __syncthreads();

#pragma unroll
    for (int i = 0; i < 4; i++)
#pragma unroll
        for (int j = 0; j < 4; j++) acc[i][j] = bs[j0 + j];

#pragma unroll 8
    for (int k = 0; k < 64; k++) {
        float4 w = *(const float4*)&Ws[k * 64 + ((tx ^ (k & 15)) << 2)];
        float x0 = Xs[(r0 + 0) * 64 + k];
        float x1 = Xs[(r0 + 1) * 64 + k];
        float x2 = Xs[(r0 + 2) * 64 + k];
        float x3 = Xs[(r0 + 3) * 64 + k];
        acc[0][0] += x0 * w.x; acc[0][1] += x0 * w.y; acc[0][2] += x0 * w.z; acc[0][3] += x0 * w.w;
        acc[1][0] += x1 * w.x; acc[1][1] += x1 * w.y; acc[1][2] += x1 * w.z; acc[1][3] += x1 * w.w;
        acc[2][0] += x2 * w.x; acc[2][1] += x2 * w.y; acc[2][2] += x2 * w.z; acc[2][3] += x2 * w.w;
        acc[3][0] += x3 * w.x; acc[3][1] += x3 * w.y; acc[3][2] += x3 * w.z; acc[3][3] += x3 * w.w;
    }

#pragma unroll
    for (int i = 0; i < 4; i++) {
        float4 y = make_float4(acc[i][0], acc[i][1], acc[i][2], acc[i][3]);
        *(float4*)&Y[(size_t)(row0 + r0 + i) * 64 + j0] = y;
    }
}

// ---------------- per-node aggregation: online softmax + masked offset min/max ----------------
// One warp per node; each lane owns features (2*lane, 2*lane+1).
__global__ __launch_bounds__(256) void aggregate_kernel(int layer) {
    const float* __restrict__ embs_in = layer ? g_embsB : g_embsA;
    const float* __restrict__ off_in  = layer ? g_offB  : g_offA;
    float* __restrict__ embs_out = layer ? g_embsA : g_embsB;
    float* __restrict__ off_out  = layer ? g_offA  : g_offB;

    int w = (blockIdx.x * blockDim.x + threadIdx.x) >> 5;
    if (w >= NNODES) return;
    int lane = threadIdx.x & 31;
    int f = lane * 2;

    int beg = g_csr_off[w];
    int end = g_csr_off[w + 1];
    const bool is_user = (w < NU);
    const bool is_item = (w >= NU) && (w < NU + NI);

    float m0 = -INFINITY, m1 = -INFINITY;
    float s0 = 0.f, s1 = 0.f, n0 = 0.f, n1 = 0.f;
    float mn0 = INFINITY, mn1 = INFINITY, mx0 = 0.f, mx1 = 0.f;

    for (int p = beg; p < end; ++p) {
        int t = g_csr_tail[p];
        size_t base = (size_t)t * 64 + f;
        float2 h = *(const float2*)(g_Hn + base);
        float2 x = *(const float2*)(embs_in + base);
        float2 o = *(const float2*)(off_in + base);
        o.x = fmaxf(o.x, 0.f);
        o.y = fmaxf(o.y, 0.f);

        // online softmax (per feature)
        float nm0 = fmaxf(m0, h.x);
        float sc0 = __expf(m0 - nm0);     // 0 on first edge (m0=-inf)
        float e0  = __expf(h.x - nm0);
        s0 = s0 * sc0 + e0;
        n0 = n0 * sc0 + e0 * x.x;
        m0 = nm0;

        float nm1 = fmaxf(m1, h.y);
        float sc1 = __expf(m1 - nm1);
        float e1  = __expf(h.y - nm1);
        s1 = s1 * sc1 + e1;
        n1 = n1 * sc1 + e1 * x.y;
        m1 = nm1;

        // masked offset reductions
        bool t_item = (t >= NU) && (t < NU + NI);
        bool t_tag  = (t >= NU + NI);
        if (is_user) {
            if (t_item) { mn0 = fminf(mn0, o.x); mn1 = fminf(mn1, o.y); }
            else if (t_tag) { mx0 = fmaxf(mx0, o.x); mx1 = fmaxf(mx1, o.y); }
        } else if (is_item) {
            mx0 = fmaxf(mx0, o.x); mx1 = fmaxf(mx1, o.y);
        } else {
            mn0 = fminf(mn0, o.x); mn1 = fminf(mn1, o.y);
        }
    }

    float a0 = (s0 > 0.f) ? n0 / s0 : 0.f;
    float a1 = (s1 > 0.f) ? n1 / s1 : 0.f;

    // row L2-normalize (warp reduction over 64 features)
    float ss = a0 * a0 + a1 * a1;
#pragma unroll
    for (int of = 16; of; of >>= 1) ss += __shfl_xor_sync(0xffffffffu, ss, of);
    float inv = 1.f / fmaxf(sqrtf(ss), 1e-12f);

    size_t ob = (size_t)w * 64 + f;
    *(float2*)(embs_out + ob) = make_float2(a0 * inv, a1 * inv);

    float o0, o1;
    if (is_user) {
        float i0 = isinf(mn0) ? 0.f : mn0;
        float i1 = isinf(mn1) ? 0.f : mn1;
        o0 = fminf(i0, mx0);   // relu(min(inter, ut)); both >= 0
        o1 = fminf(i1, mx1);
    } else if (is_item) {
        o0 = mx0; o1 = mx1;
    } else {
        o0 = isinf(mn0) ? 0.f : mn0;
        o1 = isinf(mn1) ? 0.f : mn1;
    }
    *(float2*)(off_out + ob) = make_float2(fmaxf(o0, 0.f), fmaxf(o1, 0.f));
}

// ---------------- output: (u_emb, u_off, i_emb, i_off, t_emb, t_off) ----------------
__global__ void write_out_kernel(float4* __restrict__ out) {
    int idx = blockIdx.x * blockDim.x + threadIdx.x;  // over NNODES*16 float4s
    if (idx >= NNODES * 16) return;
    int n = idx >> 4;
    int emb_base, off_base, local;
    if (n < NU) { local = idx; emb_base = 0; off_base = NU * 16; }
    else if (n < NU + NI) {
        local = idx - NU * 16;
        emb_base = 2 * NU * 16;
        off_base = 2 * NU * 16 + NI * 16;
    } else {
        local = idx - (NU + NI) * 16;
        emb_base = 2 * (NU + NI) * 16;
        off_base = 2 * (NU + NI) * 16 + NT * 16;
    }
    out[emb_base + local] = ((const float4*)g_embsA)[idx];
    out[off_base + local] = ((const float4*)g_offA)[idx];
}

// ---------------- launch ----------------
extern "C" void kernel_launch(void* const* d_in, const int* in_sizes, int n_in,
                              void* d_out, int out_size) {
    const float* user_emb = (const float*)d_in[0];
    const float* user_off = (const float*)d_in[1];
    const float* item_emb = (const float*)d_in[2];
    const float* item_off = (const float*)d_in[3];
    const float* tag_emb  = (const float*)d_in[4];
    const float* tag_off  = (const float*)d_in[5];
    const float* W1 = (const float*)d_in[6];
    const float* b1 = (const float*)d_in[7];
    const float* W2 = (const float*)d_in[8];
    const float* b2 = (const float*)d_in[9];
    const int* head = (const int*)d_in[10];
    const int* tail = (const int*)d_in[11];
    float* out = (float*)d_out;

    const int NB = (NNODES + SCAN_B - 1) / SCAN_B;  // 157

    // CSR by head (layer-invariant)
    zero_deg_kernel<<<(NNODES + 255) / 256, 256>>>();
    hist_kernel<<<(NE + 255) / 256, 256>>>(head);
    scan_block_kernel<<<NB, SCAN_B>>>();
    scan_sums_kernel<<<1, 32>>>(NB);
    scan_add_kernel<<<NB, SCAN_B>>>();
    pos_init_kernel<<<(NNODES + 255) / 256, 256>>>();
    scatter_kernel<<<(NE + 255) / 256, 256>>>(head, tail);

    // init buffers
    init_kernel<<<(NNODES * 16 + 255) / 256, 256>>>(
        (const float4*)user_emb, (const float4*)user_off,
        (const float4*)item_emb, (const float4*)item_off,
        (const float4*)tag_emb,  (const float4*)tag_off);

    // layer 1: A -> B
    mlp_kernel<<<NNODES / 64, 256>>>(0, W1, b1, W2, b2);
    aggregate_kernel<<<(NNODES + 7) / 8, 256>>>(0);

    // layer 2: B -> A
    mlp_kernel<<<NNODES / 64, 256>>>(1, W1, b1, W2, b2);
    aggregate_kernel<<<(NNODES + 7) / 8, 256>>>(1);

    write_out_kernel<<<(NNODES * 16 + 255) / 256, 256>>>((float4*)out);
}

// round 2
// speedup vs baseline: 1.0140x; 1.0140x over previous
#include <cuda_runtime.h>
#include <math.h>

#define NU 100000
#define NI 50000
#define NT 10000
#define NNODES 160000
#define NE 800000
#define DD 64

typedef unsigned long long u64;

// ---------------- device scratch (no allocations allowed) ----------------
__device__ float g_embsB[NNODES * DD];   // layer-1 normalized embeddings
__device__ float g_offB[NNODES * DD];    // layer-1 offsets (relu'd)
__device__ float g_Hn[NNODES * DD];      // per-node MLP output (current layer)

__device__ int g_deg[NNODES];
__device__ int g_scan[NNODES];
__device__ int g_csr_off[NNODES + 1];
__device__ int g_pos[NNODES];
__device__ int g_csr_tail[NE];
__device__ int g_bsums[256];

// ---------------- packed f32x2 helpers (PTX 8.6, sm_100+) ----------------
__device__ __forceinline__ u64 pack2(float a, float b) {
    u64 r; asm("mov.b64 %0,{%1,%2};" : "=l"(r) : "f"(a), "f"(b)); return r;
}
__device__ __forceinline__ float2 unpack2(u64 v) {
    float2 f; asm("mov.b64 {%0,%1},%2;" : "=f"(f.x), "=f"(f.y) : "l"(v)); return f;
}
__device__ __forceinline__ u64 ffma2(u64 a, u64 b, u64 c) {
    u64 d; asm("fma.rn.f32x2 %0,%1,%2,%3;" : "=l"(d) : "l"(a), "l"(b), "l"(c)); return d;
}

// ---------------- CSR build ----------------
__global__ void zero_deg_kernel() {
    int i = blockIdx.x * blockDim.x + threadIdx.x;
    if (i < NNODES) g_deg[i] = 0;
}

__global__ void hist_kernel(const int* __restrict__ head) {
    int e = blockIdx.x * blockDim.x + threadIdx.x;
    if (e < NE) atomicAdd(&g_deg[head[e]], 1);
}

#define SCAN_B 1024
__global__ void scan_block_kernel() {
    __shared__ int sh[SCAN_B];
    int g = blockIdx.x * SCAN_B + threadIdx.x;
    int v = (g < NNODES) ? g_deg[g] : 0;
    sh[threadIdx.x] = v;
    __syncthreads();
    for (int of = 1; of < SCAN_B; of <<= 1) {
        int t = (threadIdx.x >= of) ? sh[threadIdx.x - of] : 0;
        __syncthreads();
        sh[threadIdx.x] += t;
        __syncthreads();
    }
    if (g < NNODES) g_scan[g] = sh[threadIdx.x];
    if (threadIdx.x == SCAN_B - 1) g_bsums[blockIdx.x] = sh[threadIdx.x];
}

// parallel scan of the (<=256) block sums -> exclusive
__global__ void scan_sums_kernel(int nb) {
    __shared__ int sh[256];
    int v = (threadIdx.x < nb) ? g_bsums[threadIdx.x] : 0;
    sh[threadIdx.x] = v;
    __syncthreads();
    for (int of = 1; of < 256; of <<= 1) {
        int t = (threadIdx.x >= of) ? sh[threadIdx.x - of] : 0;
        __syncthreads();
        sh[threadIdx.x] += t;
        __syncthreads();
    }
    if (threadIdx.x < nb) g_bsums[threadIdx.x] = sh[threadIdx.x] - v;  // exclusive
    if (threadIdx.x == 0) g_csr_off[0] = 0;
}

__global__ void scan_add_kernel() {
    int g = blockIdx.x * SCAN_B + threadIdx.x;
    if (g < NNODES) {
        int inc = g_scan[g] + g_bsums[blockIdx.x];
        g_csr_off[g + 1] = inc;
        g_pos[g] = inc - g_deg[g];   // exclusive offset == fill cursor
    }
}

__global__ void scatter_kernel(const int* __restrict__ head, const int* __restrict__ tail) {
    int e = blockIdx.x * blockDim.x + threadIdx.x;
    if (e < NE) {
        int h = head[e];
        int p = atomicAdd(&g_pos[h], 1);
        g_csr_tail[p] = tail[e];
    }
}

// ---------------- fused 2-stage MLP: Hn = relu(X@W1^T+b1)@W2^T+b2 ----------------
// 64x64 tile / block, 256 threads, 4x4 per-thread tile, packed f32x2 FMAs.
// W in shared, xor-swizzled so each k-iter does one conflict-free 16B load.
// X in shared pre-DUPLICATED as {x,x} u64 so the broadcast operand is a single LDS.64.
__device__ __forceinline__ int wswz(int k, int j) {
    return k * 64 + ((((j >> 2) ^ (k & 15)) << 2) | (j & 3));
}

template <int LAYER>
__global__ __launch_bounds__(256) void mlp_kernel(
    const float* __restrict__ ue, const float* __restrict__ ie, const float* __restrict__ te,
    const float* __restrict__ W1, const float* __restrict__ b1,
    const float* __restrict__ W2, const float* __restrict__ b2) {
    __shared__ float Ws[64 * 64];        // 16 KB
    __shared__ u64 Xd[64 * 64];          // 32 KB (duplicated operand)

    int tid = threadIdx.x;
    int row0 = blockIdx.x * 64;

    // W1 transposed + swizzled
    for (int i = tid; i < 4096; i += 256) {
        int j = i >> 6, k = i & 63;
        Ws[wswz(k, j)] = W1[i];
    }
    // X tile, duplicated
    for (int i = tid; i < 1024; i += 256) {
        int rl = i >> 4, c4 = (i & 15) * 4;
        int row = row0 + rl;
        const float* src;
        if (LAYER == 0) {
            if (row < NU) src = ue + (size_t)row * 64;
            else if (row < NU + NI) src = ie + (size_t)(row - NU) * 64;
            else src = te + (size_t)(row - NU - NI) * 64;
        } else {
            src = g_embsB + (size_t)row * 64;
        }
        float4 v = *(const float4*)(src + c4);
        Xd[rl * 64 + c4 + 0] = pack2(v.x, v.x);
        Xd[rl * 64 + c4 + 1] = pack2(v.y, v.y);
        Xd[rl * 64 + c4 + 2] = pack2(v.z, v.z);
        Xd[rl * 64 + c4 + 3] = pack2(v.w, v.w);
    }
    __syncthreads();

    int tx = tid & 15, ty = tid >> 4;
    int j0 = tx * 4, r0 = ty * 4;

    u64 acc[4][2];
    {
        float4 b = *(const float4*)(b1 + j0);
        u64 p0 = pack2(b.x, b.y), p1 = pack2(b.z, b.w);
#pragma unroll
        for (int i = 0; i < 4; i++) { acc[i][0] = p0; acc[i][1] = p1; }
    }

    const u64* X0 = Xd + (r0 + 0) * 64;
    const u64* X1 = Xd + (r0 + 1) * 64;
    const u64* X2 = Xd + (r0 + 2) * 64;
    const u64* X3 = Xd + (r0 + 3) * 64;

#pragma unroll 8
    for (int k = 0; k < 64; k++) {
        ulonglong2 w = *(const ulonglong2*)&Ws[k * 64 + ((tx ^ (k & 15)) << 2)];
        u64 x0 = X0[k], x1 = X1[k], x2 = X2[k], x3 = X3[k];
        acc[0][0] = ffma2(x0, w.x, acc[0][0]); acc[0][1] = ffma2(x0, w.y, acc[0][1]);
        acc[1][0] = ffma2(x1, w.x, acc[1][0]); acc[1][1] = ffma2(x1, w.y, acc[1][1]);
        acc[2][0] = ffma2(x2, w.x, acc[2][0]); acc[2][1] = ffma2(x2, w.y, acc[2][1]);
        acc[3][0] = ffma2(x3, w.x, acc[3][0]); acc[3][1] = ffma2(x3, w.y, acc[3][1]);
    }
    __syncthreads();

    // h = relu(acc) -> Xd (duplicated, transposed store not needed: same layout)
#pragma unroll
    for (int i = 0; i < 4; i++) {
#pragma unroll
        for (int jp = 0; jp < 2; jp++) {
            float2 p = unpack2(acc[i][jp]);
            float h0 = fmaxf(p.x, 0.f), h1 = fmaxf(p.y, 0.f);
            Xd[(r0 + i) * 64 + j0 + 2 * jp + 0] = pack2(h0, h0);
            Xd[(r0 + i) * 64 + j0 + 2 * jp + 1] = pack2(h1, h1);
        }
    }
    for (int i = tid; i < 4096; i += 256) {
        int j = i >> 6, k = i & 63;
        Ws[wswz(k, j)] = W2[i];
    }
    __syncthreads();

    {
        float4 b = *(const float4*)(b2 + j0);
        u64 p0 = pack2(b.x, b.y), p1 = pack2(b.z, b.w);
#pragma unroll
        for (int i = 0; i < 4; i++) { acc[i][0] = p0; acc[i][1] = p1; }
    }

#pragma unroll 8
    for (int k = 0; k < 64; k++) {
        ulonglong2 w = *(const ulonglong2*)&Ws[k * 64 + ((tx ^ (k & 15)) << 2)];
        u64 x0 = X0[k], x1 = X1[k], x2 = X2[k], x3 = X3[k];
        acc[0][0] = ffma2(x0, w.x, acc[0][0]); acc[0][1] = ffma2(x0, w.y, acc[0][1]);
        acc[1][0] = ffma2(x1, w.x, acc[1][0]); acc[1][1] = ffma2(x1, w.y, acc[1][1]);
        acc[2][0] = ffma2(x2, w.x, acc[2][0]); acc[2][1] = ffma2(x2, w.y, acc[2][1]);
        acc[3][0] = ffma2(x3, w.x, acc[3][0]); acc[3][1] = ffma2(x3, w.y, acc[3][1]);
    }

#pragma unroll
    for (int i = 0; i < 4; i++) {
        float2 u0 = unpack2(acc[i][0]);
        float2 u1 = unpack2(acc[i][1]);
        float4 y = make_float4(u0.x, u0.y, u1.x, u1.y);
        *(float4*)&g_Hn[(size_t)(row0 + r0 + i) * 64 + j0] = y;
    }
}

// ---------------- per-node aggregation: online softmax + masked offset min/max ----------------
// One warp per node; lane owns features (2*lane, 2*lane+1). Tail indices are
// batch-loaded by lanes and broadcast via shfl (no per-edge uniform LDG).
template <int FINAL>
__global__ __launch_bounds__(256) void aggregate_kernel(
    const float* __restrict__ ue, const float* __restrict__ uo,
    const float* __restrict__ ie, const float* __restrict__ io,
    const float* __restrict__ te, const float* __restrict__ to,
    float* __restrict__ out) {
    int w = (blockIdx.x * blockDim.x + threadIdx.x) >> 5;
    if (w >= NNODES) return;
    int lane = threadIdx.x & 31;
    int f = lane * 2;

    int beg = g_csr_off[w];
    int end = g_csr_off[w + 1];
    const bool is_user = (w < NU);
    const bool is_item = (w >= NU) && (w < NU + NI);

    float m0 = -INFINITY, m1 = -INFINITY;
    float s0 = 0.f, s1 = 0.f, n0 = 0.f, n1 = 0.f;
    float mn0 = INFINITY, mn1 = INFINITY, mx0 = 0.f, mx1 = 0.f;

    for (int chunk = beg; chunk < end; chunk += 32) {
        int nn = end - chunk; if (nn > 32) nn = 32;
        int tl = 0;
        if (lane < nn) tl = g_csr_tail[chunk + lane];
        for (int q = 0; q < nn; q++) {
            int t = __shfl_sync(0xffffffffu, tl, q);
            const float* xp; const float* op;
            if (FINAL == 0) {
                if (t < NU)           { xp = ue + (size_t)t * 64;            op = uo + (size_t)t * 64; }
                else if (t < NU + NI) { xp = ie + (size_t)(t - NU) * 64;     op = io + (size_t)(t - NU) * 64; }
                else                  { xp = te + (size_t)(t - NU - NI) * 64; op = to + (size_t)(t - NU - NI) * 64; }
            } else {
                xp = g_embsB + (size_t)t * 64;
                op = g_offB + (size_t)t * 64;
            }
            float2 h = *(const float2*)(g_Hn + (size_t)t * 64 + f);
            float2 x = *(const float2*)(xp + f);
            float2 o = *(const float2*)(op + f);
            o.x = fmaxf(o.x, 0.f);
            o.y = fmaxf(o.y, 0.f);

            // online softmax (per feature)
            float nm0 = fmaxf(m0, h.x);
            float sc0 = __expf(m0 - nm0);
            float e0  = __expf(h.x - nm0);
            s0 = s0 * sc0 + e0;
            n0 = n0 * sc0 + e0 * x.x;
            m0 = nm0;

            float nm1 = fmaxf(m1, h.y);
            float sc1 = __expf(m1 - nm1);
            float e1  = __expf(h.y - nm1);
            s1 = s1 * sc1 + e1;
            n1 = n1 * sc1 + e1 * x.y;
            m1 = nm1;

            // masked offset reductions
            bool t_item = (t >= NU) && (t < NU + NI);
            bool t_tag  = (t >= NU + NI);
            if (is_user) {
                if (t_item)     { mn0 = fminf(mn0, o.x); mn1 = fminf(mn1, o.y); }
                else if (t_tag) { mx0 = fmaxf(mx0, o.x); mx1 = fmaxf(mx1, o.y); }
            } else if (is_item) {
                mx0 = fmaxf(mx0, o.x); mx1 = fmaxf(mx1, o.y);
            } else {
                mn0 = fminf(mn0, o.x); mn1 = fminf(mn1, o.y);
            }
        }
    }

    float a0 = (s0 > 0.f) ? n0 / s0 : 0.f;
    float a1 = (s1 > 0.f) ? n1 / s1 : 0.f;

    // row L2-normalize
    float ss = a0 * a0 + a1 * a1;
#pragma unroll
    for (int of = 16; of; of >>= 1) ss += __shfl_xor_sync(0xffffffffu, ss, of);
    float inv = 1.f / fmaxf(sqrtf(ss), 1e-12f);
    a0 *= inv; a1 *= inv;

    float o0, o1;
    if (is_user) {
        float i0 = isinf(mn0) ? 0.f : mn0;
        float i1 = isinf(mn1) ? 0.f : mn1;
        o0 = fminf(i0, mx0);
        o1 = fminf(i1, mx1);
    } else if (is_item) {
        o0 = mx0; o1 = mx1;
    } else {
        o0 = isinf(mn0) ? 0.f : mn0;
        o1 = isinf(mn1) ? 0.f : mn1;
    }
    o0 = fmaxf(o0, 0.f);
    o1 = fmaxf(o1, 0.f);

    if (FINAL == 0) {
        size_t ob = (size_t)w * 64 + f;
        *(float2*)(g_embsB + ob) = make_float2(a0, a1);
        *(float2*)(g_offB + ob)  = make_float2(o0, o1);
    } else {
        // write directly into final output layout:
        // [u_emb][u_off][i_emb][i_off][t_emb][t_off]
        size_t eb, ob;
        if (is_user) {
            eb = (size_t)w * 64;
            ob = (size_t)NU * 64 + (size_t)w * 64;
        } else if (is_item) {
            size_t b2 = (size_t)2 * NU * 64;
            eb = b2 + (size_t)(w - NU) * 64;
            ob = b2 + (size_t)NI * 64 + (size_t)(w - NU) * 64;
        } else {
            size_t b3 = (size_t)2 * (NU + NI) * 64;
            eb = b3 + (size_t)(w - NU - NI) * 64;
            ob = b3 + (size_t)NT * 64 + (size_t)(w - NU - NI) * 64;
        }
        *(float2*)(out + eb + f) = make_float2(a0, a1);
        *(float2*)(out + ob + f) = make_float2(o0, o1);
    }
}

// ---------------- launch ----------------
extern "C" void kernel_launch(void* const* d_in, const int* in_sizes, int n_in,
                              void* d_out, int out_size) {
    const float* user_emb = (const float*)d_in[0];
    const float* user_off = (const float*)d_in[1];
    const float* item_emb = (const float*)d_in[2];
    const float* item_off = (const float*)d_in[3];
    const float* tag_emb  = (const float*)d_in[4];
    const float* tag_off  = (const float*)d_in[5];
    const float* W1 = (const float*)d_in[6];
    const float* b1 = (const float*)d_in[7];
    const float* W2 = (const float*)d_in[8];
    const float* b2 = (const float*)d_in[9];
    const int* head = (const int*)d_in[10];
    const int* tail = (const int*)d_in[11];
    float* out = (float*)d_out;

    const int NB = (NNODES + SCAN_B - 1) / SCAN_B;  // 157

    // CSR by head (layer-invariant)
    zero_deg_kernel<<<(NNODES + 255) / 256, 256>>>();
    hist_kernel<<<(NE + 255) / 256, 256>>>(head);
    scan_block_kernel<<<NB, SCAN_B>>>();
    scan_sums_kernel<<<1, 256>>>(NB);
    scan_add_kernel<<<NB, SCAN_B>>>();
    scatter_kernel<<<(NE + 255) / 256, 256>>>(head, tail);

    // layer 1: inputs -> g_embsB / g_offB
    mlp_kernel<0><<<NNODES / 64, 256>>>(user_emb, item_emb, tag_emb, W1, b1, W2, b2);
    aggregate_kernel<0><<<(NNODES + 7) / 8, 256>>>(
        user_emb, user_off, item_emb, item_off, tag_emb, tag_off, out);

    // layer 2: g_embsB / g_offB -> d_out (final layout)
    mlp_kernel<1><<<NNODES / 64, 256>>>(user_emb, item_emb, tag_emb, W1, b1, W2, b2);
    aggregate_kernel<1><<<(NNODES + 7) / 8, 256>>>(
        user_emb, user_off, item_emb, item_off, tag_emb, tag_off, out);
}

// round 4
// speedup vs baseline: 1.0274x; 1.0132x over previous
#include <cuda_runtime.h>
#include <math.h>

#define NU 100000
#define NI 50000
#define NT 10000
#define NNODES 160000
#define NE 800000
#define DD 64

typedef unsigned long long u64;

// ---------------- device scratch ----------------
__device__ float g_embsB[NNODES * DD];     // layer-1 normalized embeddings
__device__ float g_offB[NNODES * DD];      // layer-1 offsets (relu'd)
__device__ float g_EP[NNODES * 128];       // per node: [0:64) eh=exp(h), [64:128) px=eh*x

__device__ int g_deg[NNODES];
__device__ int g_scan[NNODES];
__device__ int g_csr_off[NNODES + 1];
__device__ int g_pos[NNODES];
__device__ int g_csr_tail[NE];
__device__ int g_bsums[256];

// ---------------- packed f32x2 helpers ----------------
__device__ __forceinline__ u64 pack2(float a, float b) {
    u64 r; asm("mov.b64 %0,{%1,%2};" : "=l"(r) : "f"(a), "f"(b)); return r;
}
__device__ __forceinline__ float2 unpack2(u64 v) {
    float2 f; asm("mov.b64 {%0,%1},%2;" : "=f"(f.x), "=f"(f.y) : "l"(v)); return f;
}
__device__ __forceinline__ u64 ffma2(u64 a, u64 b, u64 c) {
    u64 d; asm("fma.rn.f32x2 %0,%1,%2,%3;" : "=l"(d) : "l"(a), "l"(b), "l"(c)); return d;
}

// ---------------- CSR build ----------------
__global__ void zero_deg_kernel() {
    int i = blockIdx.x * blockDim.x + threadIdx.x;
    if (i < NNODES) g_deg[i] = 0;
}

__global__ void hist_kernel(const int* __restrict__ head) {
    int e = blockIdx.x * blockDim.x + threadIdx.x;
    if (e < NE) atomicAdd(&g_deg[head[e]], 1);
}

#define SCAN_B 1024
__global__ void scan_block_kernel() {
    __shared__ int sh[SCAN_B];
    int g = blockIdx.x * SCAN_B + threadIdx.x;
    int v = (g < NNODES) ? g_deg[g] : 0;
    sh[threadIdx.x] = v;
    __syncthreads();
    for (int of = 1; of < SCAN_B; of <<= 1) {
        int t = (threadIdx.x >= of) ? sh[threadIdx.x - of] : 0;
        __syncthreads();
        sh[threadIdx.x] += t;
        __syncthreads();
    }
    if (g < NNODES) g_scan[g] = sh[threadIdx.x];
    if (threadIdx.x == SCAN_B - 1) g_bsums[blockIdx.x] = sh[threadIdx.x];
}

__global__ void scan_sums_kernel(int nb) {
    __shared__ int sh[256];
    int v = (threadIdx.x < nb) ? g_bsums[threadIdx.x] : 0;
    sh[threadIdx.x] = v;
    __syncthreads();
    for (int of = 1; of < 256; of <<= 1) {
        int t = (threadIdx.x >= of) ? sh[threadIdx.x - of] : 0;
        __syncthreads();
        sh[threadIdx.x] += t;
        __syncthreads();
    }
    if (threadIdx.x < nb) g_bsums[threadIdx.x] = sh[threadIdx.x] - v;  // exclusive
    if (threadIdx.x == 0) g_csr_off[0] = 0;
}

__global__ void scan_add_kernel() {
    int g = blockIdx.x * SCAN_B + threadIdx.x;
    if (g < NNODES) {
        int inc = g_scan[g] + g_bsums[blockIdx.x];
        g_csr_off[g + 1] = inc;
        g_pos[g] = inc - g_deg[g];
    }
}

__global__ void scatter_kernel(const int* __restrict__ head, const int* __restrict__ tail) {
    int e = blockIdx.x * blockDim.x + threadIdx.x;
    if (e < NE) {
        int h = head[e];
        int p = atomicAdd(&g_pos[h], 1);
        g_csr_tail[p] = tail[e];
    }
}

// ---------------- fused 2-stage MLP + exp/px epilogue ----------------
// Writes g_EP[row][0:64) = exp(MLP(x)),  g_EP[row][64:128) = exp(MLP(x)) * x
__device__ __forceinline__ int wswz(int k, int j) {
    return k * 64 + ((((j >> 2) ^ (k & 15)) << 2) | (j & 3));
}

template <int LAYER>
__global__ __launch_bounds__(256) void mlp_kernel(
    const float* __restrict__ ue, const float* __restrict__ ie, const float* __restrict__ te,
    const float* __restrict__ W1, const float* __restrict__ b1,
    const float* __restrict__ W2, const float* __restrict__ b2) {
    __shared__ float Ws[64 * 64];        // 16 KB
    __shared__ u64 Xd[64 * 64];          // 32 KB (duplicated operand)

    int tid = threadIdx.x;
    int row0 = blockIdx.x * 64;

    for (int i = tid; i < 4096; i += 256) {
        int j = i >> 6, k = i & 63;
        Ws[wswz(k, j)] = W1[i];
    }
    for (int i = tid; i < 1024; i += 256) {
        int rl = i >> 4, c4 = (i & 15) * 4;
        int row = row0 + rl;
        const float* src;
        if (LAYER == 0) {
            if (row < NU) src = ue + (size_t)row * 64;
            else if (row < NU + NI) src = ie + (size_t)(row - NU) * 64;
            else src = te + (size_t)(row - NU - NI) * 64;
        } else {
            src = g_embsB + (size_t)row * 64;
        }
        float4 v = *(const float4*)(src + c4);
        Xd[rl * 64 + c4 + 0] = pack2(v.x, v.x);
        Xd[rl * 64 + c4 + 1] = pack2(v.y, v.y);
        Xd[rl * 64 + c4 + 2] = pack2(v.z, v.z);
        Xd[rl * 64 + c4 + 3] = pack2(v.w, v.w);
    }
    __syncthreads();

    int tx = tid & 15, ty = tid >> 4;
    int j0 = tx * 4, r0 = ty * 4;

    u64 acc[4][2];
    {
        float4 b = *(const float4*)(b1 + j0);
        u64 p0 = pack2(b.x, b.y), p1 = pack2(b.z, b.w);
#pragma unroll
        for (int i = 0; i < 4; i++) { acc[i][0] = p0; acc[i][1] = p1; }
    }

    const u64* X0 = Xd + (r0 + 0) * 64;
    const u64* X1 = Xd + (r0 + 1) * 64;
    const u64* X2 = Xd + (r0 + 2) * 64;
    const u64* X3 = Xd + (r0 + 3) * 64;

#pragma unroll 8
    for (int k = 0; k < 64; k++) {
        ulonglong2 w = *(const ulonglong2*)&Ws[k * 64 + ((tx ^ (k & 15)) << 2)];
        u64 x0 = X0[k], x1 = X1[k], x2 = X2[k], x3 = X3[k];
        acc[0][0] = ffma2(x0, w.x, acc[0][0]); acc[0][1] = ffma2(x0, w.y, acc[0][1]);
        acc[1][0] = ffma2(x1, w.x, acc[1][0]); acc[1][1] = ffma2(x1, w.y, acc[1][1]);
        acc[2][0] = ffma2(x2, w.x, acc[2][0]); acc[2][1] = ffma2(x2, w.y, acc[2][1]);
        acc[3][0] = ffma2(x3, w.x, acc[3][0]); acc[3][1] = ffma2(x3, w.y, acc[3][1]);
    }
    __syncthreads();

#pragma unroll
    for (int i = 0; i < 4; i++) {
#pragma unroll
        for (int jp = 0; jp < 2; jp++) {
            float2 p = unpack2(acc[i][jp]);
            float h0 = fmaxf(p.x, 0.f), h1 = fmaxf(p.y, 0.f);
            Xd[(r0 + i) * 64 + j0 + 2 * jp + 0] = pack2(h0, h0);
            Xd[(r0 + i) * 64 + j0 + 2 * jp + 1] = pack2(h1, h1);
        }
    }
    for (int i = tid; i < 4096; i += 256) {
        int j = i >> 6, k = i & 63;
        Ws[wswz(k, j)] = W2[i];
    }
    __syncthreads();

    {
        float4 b = *(const float4*)(b2 + j0);
        u64 p0 = pack2(b.x, b.y), p1 = pack2(b.z, b.w);
#pragma unroll
        for (int i = 0; i < 4; i++) { acc[i][0] = p0; acc[i][1] = p1; }
    }

#pragma unroll 8
    for (int k = 0; k < 64; k++) {
        ulonglong2 w = *(const ulonglong2*)&Ws[k * 64 + ((tx ^ (k & 15)) << 2)];
        u64 x0 = X0[k], x1 = X1[k], x2 = X2[k], x3 = X3[k];
        acc[0][0] = ffma2(x0, w.x, acc[0][0]); acc[0][1] = ffma2(x0, w.y, acc[0][1]);
        acc[1][0] = ffma2(x1, w.x, acc[1][0]); acc[1][1] = ffma2(x1, w.y, acc[1][1]);
        acc[2][0] = ffma2(x2, w.x, acc[2][0]); acc[2][1] = ffma2(x2, w.y, acc[2][1]);
        acc[3][0] = ffma2(x3, w.x, acc[3][0]); acc[3][1] = ffma2(x3, w.y, acc[3][1]);
    }

    // epilogue: eh = exp(y), px = eh * x  (x reloaded from source; L2-hot)
#pragma unroll
    for (int i = 0; i < 4; i++) {
        int row = row0 + r0 + i;
        const float* src;
        if (LAYER == 0) {
            if (row < NU) src = ue + (size_t)row * 64;
            else if (row < NU + NI) src = ie + (size_t)(row - NU) * 64;
            else src = te + (size_t)(row - NU - NI) * 64;
        } else {
            src = g_embsB + (size_t)row * 64;
        }
        float4 xv = *(const float4*)(src + j0);
        float2 u0 = unpack2(acc[i][0]);
        float2 u1 = unpack2(acc[i][1]);
        float e0 = __expf(u0.x), e1 = __expf(u0.y);
        float e2 = __expf(u1.x), e3 = __expf(u1.y);
        size_t base = (size_t)row * 128;
        *(float4*)&g_EP[base + j0]      = make_float4(e0, e1, e2, e3);
        *(float4*)&g_EP[base + 64 + j0] = make_float4(e0 * xv.x, e1 * xv.y, e2 * xv.z, e3 * xv.w);
    }
}

// ---------------- per-node aggregation: commutative sums + masked min/max ----------------
// One warp per node, 2 edges per iteration: lanes 0-15 even edge, 16-31 odd edge,
// each lane owns 4 features (float4 loads). Halves merged with shfl_xor(16).
template <int FINAL>
__global__ __launch_bounds__(256) void aggregate_kernel(
    const float* __restrict__ uo, const float* __restrict__ io, const float* __restrict__ to,
    float* __restrict__ out) {
    int w = (blockIdx.x * blockDim.x + threadIdx.x) >> 5;
    if (w >= NNODES) return;
    int lane = threadIdx.x & 31;
    int half = lane >> 4;
    int fl = (lane & 15) * 4;

    int beg = g_csr_off[w];
    int end = g_csr_off[w + 1];
    const bool is_user = (w < NU);
    const bool is_item = (w >= NU) && (w < NU + NI);

    float4 s = make_float4(0.f, 0.f, 0.f, 0.f);
    float4 n = make_float4(0.f, 0.f, 0.f, 0.f);
    float4 mn = make_float4(INFINITY, INFINITY, INFINITY, INFINITY);
    float4 mx = make_float4(0.f, 0.f, 0.f, 0.f);

    for (int chunk = beg; chunk < end; chunk += 32) {
        int nn = end - chunk; if (nn > 32) nn = 32;
        int tl = 0;
        if (lane < nn) tl = g_csr_tail[chunk + lane];
#pragma unroll 2
        for (int q = 0; q < nn; q += 2) {
            int idx = q + half;
            int t = __shfl_sync(0xffffffffu, tl, idx & 31);
            if (idx < nn) {
                size_t epb = (size_t)t * 128;
                float4 eh = *(const float4*)&g_EP[epb + fl];
                float4 px = *(const float4*)&g_EP[epb + 64 + fl];
                const float* op;
                if (FINAL == 0) {
                    if (t < NU)           op = uo + (size_t)t * 64;
                    else if (t < NU + NI) op = io + (size_t)(t - NU) * 64;
                    else                  op = to + (size_t)(t - NU - NI) * 64;
                } else {
                    op = g_offB + (size_t)t * 64;
                }
                float4 o = *(const float4*)(op + fl);
                if (FINAL == 0) {  // g_offB is already relu'd; inputs are not
                    o.x = fmaxf(o.x, 0.f); o.y = fmaxf(o.y, 0.f);
                    o.z = fmaxf(o.z, 0.f); o.w = fmaxf(o.w, 0.f);
                }

                s.x += eh.x; s.y += eh.y; s.z += eh.z; s.w += eh.w;
                n.x += px.x; n.y += px.y; n.z += px.z; n.w += px.w;

                bool t_item = (t >= NU) && (t < NU + NI);
                bool t_tag  = (t >= NU + NI);
                bool do_min = is_user ? t_item : (!is_item);
                bool do_max = is_user ? t_tag  : is_item;
                if (do_min) {
                    mn.x = fminf(mn.x, o.x); mn.y = fminf(mn.y, o.y);
                    mn.z = fminf(mn.z, o.z); mn.w = fminf(mn.w, o.w);
                }
                if (do_max) {
                    mx.x = fmaxf(mx.x, o.x); mx.y = fmaxf(mx.y, o.y);
                    mx.z = fmaxf(mx.z, o.z); mx.w = fmaxf(mx.w, o.w);
                }
            }
        }
    }

    // merge the two half-warps (feature sets are identical across halves)
#define MRG_ADD(v) v += __shfl_xor_sync(0xffffffffu, v, 16)
#define MRG_MIN(v) v = fminf(v, __shfl_xor_sync(0xffffffffu, v, 16))
#define MRG_MAX(v) v = fmaxf(v, __shfl_xor_sync(0xffffffffu, v, 16))
    MRG_ADD(s.x); MRG_ADD(s.y); MRG_ADD(s.z); MRG_ADD(s.w);
    MRG_ADD(n.x); MRG_ADD(n.y); MRG_ADD(n.z); MRG_ADD(n.w);
    MRG_MIN(mn.x); MRG_MIN(mn.y); MRG_MIN(mn.z); MRG_MIN(mn.w);
    MRG_MAX(mx.x); MRG_MAX(mx.y); MRG_MAX(mx.z); MRG_MAX(mx.w);

    float4 a;
    a.x = (s.x > 0.f) ? n.x / s.x : 0.f;
    a.y = (s.y > 0.f) ? n.y / s.y : 0.f;
    a.z = (s.z > 0.f) ? n.z / s.z : 0.f;
    a.w = (s.w > 0.f) ? n.w / s.w : 0.f;

    // row L2-normalize: features are distinct across 16-lane group
    float ss = a.x * a.x + a.y * a.y + a.z * a.z + a.w * a.w;
#pragma unroll
    for (int of = 8; of; of >>= 1) ss += __shfl_xor_sync(0xffffffffu, ss, of);
    float inv = 1.f / fmaxf(sqrtf(ss), 1e-12f);
    a.x *= inv; a.y *= inv; a.z *= inv; a.w *= inv;

    float4 ov;
    if (is_user) {
        float i0 = isinf(mn.x) ? 0.f : mn.x;
        float i1 = isinf(mn.y) ? 0.f : mn.y;
        float i2 = isinf(mn.z) ? 0.f : mn.z;
        float i3 = isinf(mn.w) ? 0.f : mn.w;
        ov = make_float4(fminf(i0, mx.x), fminf(i1, mx.y), fminf(i2, mx.z), fminf(i3, mx.w));
    } else if (is_item) {
        ov = mx;
    } else {
        ov.x = isinf(mn.x) ? 0.f : mn.x;
        ov.y = isinf(mn.y) ? 0.f : mn.y;
        ov.z = isinf(mn.z) ? 0.f : mn.z;
        ov.w = isinf(mn.w) ? 0.f : mn.w;
    }
    ov.x = fmaxf(ov.x, 0.f); ov.y = fmaxf(ov.y, 0.f);
    ov.z = fmaxf(ov.z, 0.f); ov.w = fmaxf(ov.w, 0.f);

    if (FINAL == 0) {
        size_t base = (size_t)w * 64 + fl;
        if (half == 0) *(float4*)(g_embsB + base) = a;
        else           *(float4*)(g_offB + base)  = ov;
    } else {
        size_t eb, ob;
        if (is_user) {
            eb = (size_t)w * 64;
            ob = (size_t)NU * 64 + (size_t)w * 64;
        } else if (is_item) {
            size_t b2 = (size_t)2 * NU * 64;
            eb = b2 + (size_t)(w - NU) * 64;
            ob = b2 + (size_t)NI * 64 + (size_t)(w - NU) * 64;
        } else {
            size_t b3 = (size_t)2 * (NU + NI) * 64;
            eb = b3 + (size_t)(w - NU - NI) * 64;
            ob = b3 + (size_t)NT * 64 + (size_t)(w - NU - NI) * 64;
        }
        if (half == 0) *(float4*)(out + eb + fl) = a;
        else           *(float4*)(out + ob + fl) = ov;
    }
}

// ---------------- launch ----------------
extern "C" void kernel_launch(void* const* d_in, const int* in_sizes, int n_in,
                              void* d_out, int out_size) {
    const float* user_emb = (const float*)d_in[0];
    const float* user_off = (const float*)d_in[1];
    const float* item_emb = (const float*)d_in[2];
    const float* item_off = (const float*)d_in[3];
    const float* tag_emb  = (const float*)d_in[4];
    const float* tag_off  = (const float*)d_in[5];
    const float* W1 = (const float*)d_in[6];
    const float* b1 = (const float*)d_in[7];
    const float* W2 = (const float*)d_in[8];
    const float* b2 = (const float*)d_in[9];
    const int* head = (const int*)d_in[10];
    const int* tail = (const int*)d_in[11];
    float* out = (float*)d_out;

    const int NB = (NNODES + SCAN_B - 1) / SCAN_B;

    zero_deg_kernel<<<(NNODES + 255) / 256, 256>>>();
    hist_kernel<<<(NE + 255) / 256, 256>>>(head);
    scan_block_kernel<<<NB, SCAN_B>>>();
    scan_sums_kernel<<<1, 256>>>(NB);
    scan_add_kernel<<<NB, SCAN_B>>>();
    scatter_kernel<<<(NE + 255) / 256, 256>>>(head, tail);

    // layer 1
    mlp_kernel<0><<<NNODES / 64, 256>>>(user_emb, item_emb, tag_emb, W1, b1, W2, b2);
    aggregate_kernel<0><<<(NNODES + 7) / 8, 256>>>(user_off, item_off, tag_off, out);

    // layer 2
    mlp_kernel<1><<<NNODES / 64, 256>>>(user_emb, item_emb, tag_emb, W1, b1, W2, b2);
    aggregate_kernel<1><<<(NNODES + 7) / 8, 256>>>(user_off, item_off, tag_off, out);
}